// round 15
// baseline (speedup 1.0000x reference)
#include <cuda_runtime.h>
#include <cuda_fp16.h>
#include <math.h>
#include <stdint.h>

#define MAX_E 3200000
#define MAX_N 100000
#define FIN 128
#define H1D 64
#define H2D 32
#define NCLS 10
#define SCAN_B 512
#define MAX_BLKS ((MAX_N + SCAN_B) / SCAN_B + 2)

// ---------------- scratch (device globals; referenced directly, no host APIs)
__device__ __align__(16) int    g_indeg[MAX_N];
__device__ __align__(16) int    g_off[MAX_N + 1];
__device__ __align__(16) int    g_pos[MAX_N];
__device__ __align__(16) int    g_part[MAX_N];
__device__ __align__(16) int    g_bsum[MAX_BLKS];
__device__ __align__(16) float  g_dinv[MAX_N];
__device__ __align__(16) int2   g_edge[MAX_E];       // (src, norm bits)
__device__ __align__(16) __half g_h1[MAX_N * H1D];   // fp16 storage for gather
__device__ __align__(16) float  g_a1[MAX_N * H1D];
__device__ __align__(16) __half g_h2[MAX_N * H2D];   // fp16 storage for gather

// ---------------- f32x2 helpers ----------------------------------------------
__device__ __forceinline__ uint64_t pk2(float lo, float hi) {
    uint64_t r; asm("mov.b64 %0, {%1,%2};" : "=l"(r) : "f"(lo), "f"(hi)); return r;
}
__device__ __forceinline__ void upk2(uint64_t v, float& lo, float& hi) {
    asm("mov.b64 {%0,%1}, %2;" : "=f"(lo), "=f"(hi) : "l"(v));
}
__device__ __forceinline__ void fma2(uint64_t& d, uint64_t a, uint64_t b) {
    asm("fma.rn.f32x2 %0, %1, %2, %0;" : "+l"(d) : "l"(a), "l"(b));
}

struct alignas(16) H8 { __half2 a, b, c, d; };  // 8 halves = 16B store

// ---------------- CSR build ---------------------------------------------------
__global__ void k_zero(int N) {
    int i = blockIdx.x * blockDim.x + threadIdx.x;
    if (i < N) g_indeg[i] = 0;
}

__global__ void k_count(const int* __restrict__ ei, int E) {
    int e = blockIdx.x * blockDim.x + threadIdx.x;
    if (e >= E) return;
    atomicAdd(&g_indeg[ei[e + E]], 1);
}

__global__ void k_scan1(int N) {
    __shared__ int sm[SCAN_B];
    int gid = blockIdx.x * SCAN_B + threadIdx.x;
    int v = (gid < N) ? g_indeg[gid] : 0;
    sm[threadIdx.x] = v;
    __syncthreads();
#pragma unroll
    for (int s = 1; s < SCAN_B; s <<= 1) {
        int t = (threadIdx.x >= (unsigned)s) ? sm[threadIdx.x - s] : 0;
        __syncthreads();
        sm[threadIdx.x] += t;
        __syncthreads();
    }
    if (gid < N) g_part[gid] = sm[threadIdx.x] - v;
    if (threadIdx.x == SCAN_B - 1) g_bsum[blockIdx.x] = sm[threadIdx.x];
}

__global__ void k_scan2(int nb) {
    __shared__ int sm[256];
    int t = threadIdx.x;
    int v = (t < nb) ? g_bsum[t] : 0;
    sm[t] = v;
    __syncthreads();
#pragma unroll
    for (int s = 1; s < 256; s <<= 1) {
        int u = (t >= (unsigned)s) ? sm[t - s] : 0;
        __syncthreads();
        sm[t] += u;
        __syncthreads();
    }
    if (t < nb) g_bsum[t] = sm[t] - v;
}

__global__ void k_scan3(int N, int E) {
    int gid = blockIdx.x * blockDim.x + threadIdx.x;
    if (gid < N) {
        int o = g_part[gid] + g_bsum[gid / SCAN_B];
        g_off[gid] = o;
        g_pos[gid] = o;
    }
    if (gid == 0) g_off[N] = E;
}

__global__ void k_dinv(int N) {
    int i = blockIdx.x * blockDim.x + threadIdx.x;
    if (i < N) g_dinv[i] = rsqrtf((float)g_indeg[i] + 1.0f);
}

__global__ void k_fill(const int* __restrict__ ei, int E) {
    int e = blockIdx.x * blockDim.x + threadIdx.x;
    if (e >= E) return;
    int s = ei[e];
    int d = ei[e + E];
    int p = atomicAdd(&g_pos[d], 1);
    g_edge[p] = make_int2(s, __float_as_int(g_dinv[s] * g_dinv[d]));
}

// ---------------- f32x2 GEMM: out(fp16) = (relu?)X @ W ------------------------
template <int KDIM, int ODIM, bool RELU_IN, int LAYER, int RT>
__global__ void __launch_bounds__(256, 2)
k_gemm2x(const float* __restrict__ Xparam, const float* __restrict__ Wg, int N) {
    constexpr int KC   = 32;
    constexpr int COLG = ODIM / 8;
    constexpr int ROWG = 256 / COLG;
    constexpr int TM   = ROWG * RT;
    constexpr int XP   = TM + 4;

    const float* X  = (LAYER == 1) ? Xparam : g_a1;
    __half*     out = (LAYER == 1) ? g_h1   : g_h2;

    __shared__ float Xs[KC][XP];
    __shared__ float Ws[KC][ODIM];

    int tid  = threadIdx.x;
    int row0 = blockIdx.x * TM;
    int tx = tid % COLG, ty = tid / COLG;
    int c0 = tx * 8, r0 = ty * RT;

    uint64_t acc[RT][4];
#pragma unroll
    for (int r = 0; r < RT; r++)
#pragma unroll
        for (int p = 0; p < 4; p++) acc[r][p] = 0ULL;

    for (int k0 = 0; k0 < KDIM; k0 += KC) {
        __syncthreads();
        {
            const float4* src = (const float4*)(Wg + (size_t)k0 * ODIM);
            float4* dst = (float4*)&Ws[0][0];
            for (int i = tid; i < KC * ODIM / 4; i += 256) dst[i] = src[i];
        }
        for (int i = tid; i < TM * (KC / 4); i += 256) {
            int r = i / (KC / 4);
            int q = i - r * (KC / 4);
            int gr = row0 + r;
            float4 v = make_float4(0.f, 0.f, 0.f, 0.f);
            if (gr < N) v = *(const float4*)(X + (size_t)gr * KDIM + k0 + q * 4);
            if (RELU_IN) {
                v.x = fmaxf(v.x, 0.f); v.y = fmaxf(v.y, 0.f);
                v.z = fmaxf(v.z, 0.f); v.w = fmaxf(v.w, 0.f);
            }
            Xs[q * 4 + 0][r] = v.x;
            Xs[q * 4 + 1][r] = v.y;
            Xs[q * 4 + 2][r] = v.z;
            Xs[q * 4 + 3][r] = v.w;
        }
        __syncthreads();

#pragma unroll 4
        for (int k = 0; k < KC; k++) {
            ulonglong2 wa = *(const ulonglong2*)&Ws[k][c0];
            ulonglong2 wb = *(const ulonglong2*)&Ws[k][c0 + 4];
            uint64_t wp[4] = {wa.x, wa.y, wb.x, wb.y};
#pragma unroll
            for (int rr = 0; rr < RT / 4; rr++) {
                float4 xv = *(const float4*)&Xs[k][r0 + rr * 4];
                uint64_t xb[4] = {pk2(xv.x, xv.x), pk2(xv.y, xv.y),
                                  pk2(xv.z, xv.z), pk2(xv.w, xv.w)};
#pragma unroll
                for (int r = 0; r < 4; r++)
#pragma unroll
                    for (int p = 0; p < 4; p++)
                        fma2(acc[rr * 4 + r][p], xb[r], wp[p]);
            }
        }
    }

#pragma unroll
    for (int r = 0; r < RT; r++) {
        int gr = row0 + r0 + r;
        if (gr >= N) continue;
        float4 o0, o1;
        upk2(acc[r][0], o0.x, o0.y); upk2(acc[r][1], o0.z, o0.w);
        upk2(acc[r][2], o1.x, o1.y); upk2(acc[r][3], o1.z, o1.w);
        H8 hpk;
        hpk.a = __floats2half2_rn(o0.x, o0.y);
        hpk.b = __floats2half2_rn(o0.z, o0.w);
        hpk.c = __floats2half2_rn(o1.x, o1.y);
        hpk.d = __floats2half2_rn(o1.z, o1.w);
        *(H8*)(out + (size_t)gr * ODIM + c0) = hpk;
    }
}

// -------- CSR gather layer 1 (F=64): warp-coop meta + half2 rows -------------
__global__ void k_gather64(const float* __restrict__ b, int N) {
    const __half2* h = (const __half2*)g_h1;
    float2*      out = (float2*)g_a1;
    constexpr int C2 = H1D / 2;

    int node = blockIdx.x * (blockDim.x >> 5) + (threadIdx.x >> 5);
    int lane = threadIdx.x & 31;
    if (node >= N) return;

    int beg = g_off[node];
    int end = g_off[node + 1];

    float ax = 0.0f, ay = 0.0f;
    int j = beg;
    for (; j + 32 <= end; j += 32) {
        int2 m = __ldg(&g_edge[j + lane]);
#pragma unroll 8
        for (int k = 0; k < 32; k++) {
            int   s  = __shfl_sync(0xffffffffu, m.x, k);
            float nm = __int_as_float(__shfl_sync(0xffffffffu, m.y, k));
            float2 v = __half22float2(__ldg(&h[(size_t)s * C2 + lane]));
            ax += v.x * nm;
            ay += v.y * nm;
        }
    }
    int rem = end - j;
    if (rem > 0) {
        int2 m = (lane < rem) ? __ldg(&g_edge[j + lane]) : make_int2(0, 0);
        for (int k = 0; k < rem; k++) {
            int   s  = __shfl_sync(0xffffffffu, m.x, k);
            float nm = __int_as_float(__shfl_sync(0xffffffffu, m.y, k));
            float2 v = __half22float2(__ldg(&h[(size_t)s * C2 + lane]));
            ax += v.x * nm;
            ay += v.y * nm;
        }
    }

    float di = g_dinv[node];
    float d2 = di * di;
    float2 hv = __half22float2(((const __half2*)g_h1)[(size_t)node * C2 + lane]);
    float2 bv = ((const float2*)b)[lane];
    float2 o;
    o.x = ax + hv.x * d2 + bv.x;
    o.y = ay + hv.y * d2 + bv.y;
    out[(size_t)node * C2 + lane] = o;
}

// -------- CSR gather layer 2 (F=32, fp16) + relu + classifier + log_softmax --
__global__ void k_gather32f(const float* __restrict__ b, const float* __restrict__ Wc,
                            const float* __restrict__ bc, float* __restrict__ outp,
                            int N) {
    constexpr int F = H2D;
    __shared__ float WcSm[H2D * NCLS];
    __shared__ float bcSm[NCLS];
    int tid = threadIdx.x;
    for (int i = tid; i < H2D * NCLS; i += blockDim.x) WcSm[i] = Wc[i];
    if (tid < NCLS) bcSm[tid] = bc[tid];
    __syncthreads();

    int node = blockIdx.x * (blockDim.x >> 5) + (tid >> 5);
    int lane = tid & 31;
    if (node >= N) return;

    const __half* h = g_h2;
    int beg = g_off[node];
    int end = g_off[node + 1];

    float acc = 0.0f;
    int j = beg;
    for (; j + 32 <= end; j += 32) {
        int2 m = __ldg(&g_edge[j + lane]);
#pragma unroll 8
        for (int k = 0; k < 32; k++) {
            int   s  = __shfl_sync(0xffffffffu, m.x, k);
            float nm = __int_as_float(__shfl_sync(0xffffffffu, m.y, k));
            acc += __half2float(__ldg(&h[(size_t)s * F + lane])) * nm;
        }
    }
    int rem = end - j;
    if (rem > 0) {
        int2 m = (lane < rem) ? __ldg(&g_edge[j + lane]) : make_int2(0, 0);
        for (int k = 0; k < rem; k++) {
            int   s  = __shfl_sync(0xffffffffu, m.x, k);
            float nm = __int_as_float(__shfl_sync(0xffffffffu, m.y, k));
            acc += __half2float(__ldg(&h[(size_t)s * F + lane])) * nm;
        }
    }

    float di = g_dinv[node];
    float x = acc + __half2float(h[(size_t)node * F + lane]) * di * di + b[lane];
    x = fmaxf(x, 0.0f);

    float p[NCLS];
#pragma unroll
    for (int c = 0; c < NCLS; c++) p[c] = x * WcSm[lane * NCLS + c];
#pragma unroll
    for (int s = 16; s > 0; s >>= 1)
#pragma unroll
        for (int c = 0; c < NCLS; c++)
            p[c] += __shfl_xor_sync(0xffffffffu, p[c], s);

    float lg[NCLS];
#pragma unroll
    for (int c = 0; c < NCLS; c++) lg[c] = p[c] + bcSm[c];
    float mx = lg[0];
#pragma unroll
    for (int c = 1; c < NCLS; c++) mx = fmaxf(mx, lg[c]);
    float sum = 0.0f;
#pragma unroll
    for (int c = 0; c < NCLS; c++) sum += __expf(lg[c] - mx);
    float lse = mx + logf(sum);

    if (lane < NCLS) outp[(size_t)node * NCLS + lane] = lg[lane] - lse;
}

// ---------------- launch (kernel launches ONLY; graph-capture clean) ---------
extern "C" void kernel_launch(void* const* d_in, const int* in_sizes, int n_in,
                              void* d_out, int out_size) {
    const float* feat = (const float*)d_in[0];
    const int*   ei   = (const int*)d_in[1];    // int32 (JAX x64 disabled)
    const float* W1   = (const float*)d_in[2];
    const float* b1   = (const float*)d_in[3];
    const float* W2   = (const float*)d_in[4];
    const float* b2   = (const float*)d_in[5];
    const float* Wc   = (const float*)d_in[6];
    const float* bc   = (const float*)d_in[7];

    int N = in_sizes[0] / FIN;
    int E = in_sizes[1] / 2;

    const int T = 256;
    int nb = (N + SCAN_B - 1) / SCAN_B;

    // CSR build (gemm1 at slot 4 so ncu profiles it)
    k_zero<<<(N + T - 1) / T, T>>>(N);
    k_count<<<(E + T - 1) / T, T>>>(ei, E);
    k_scan1<<<nb, SCAN_B>>>(N);
    k_gemm2x<FIN, H1D, false, 1, 8><<<(N + 255) / 256, 256>>>(feat, W1, N);  // #4
    k_scan2<<<1, 256>>>(nb);
    k_scan3<<<(N + T - 1) / T, T>>>(N, E);
    k_dinv<<<(N + T - 1) / T, T>>>(N);
    k_fill<<<(E + T - 1) / T, T>>>(ei, E);

    // layer 1 aggregation — DIAGNOSTIC: launched twice (idempotent, no atomics,
    // identical output). dur delta vs R14 == true cost of one k_gather64.
    k_gather64<<<(N + 7) / 8, 256>>>(b1, N);
    k_gather64<<<(N + 7) / 8, 256>>>(b1, N);

    // layer 2 + fused classifier/log_softmax
    k_gemm2x<H1D, H2D, true, 2, 4><<<(N + 255) / 256, 256>>>(nullptr, W2, N);
    k_gather32f<<<(N + 7) / 8, 256>>>(b2, Wc, bc, (float*)d_out, N);
}

// round 16
// speedup vs baseline: 1.1808x; 1.1808x over previous
#include <cuda_runtime.h>
#include <cuda_fp16.h>
#include <math.h>
#include <stdint.h>

#define MAX_E 3200000
#define MAX_N 100000
#define FIN 128
#define H1D 64
#define H2D 32
#define NCLS 10
#define SCAN_B 512
#define MAX_BLKS ((MAX_N + SCAN_B) / SCAN_B + 2)

// ---------------- scratch (device globals; referenced directly, no host APIs)
__device__ __align__(16) int    g_indeg[MAX_N];
__device__ __align__(16) int    g_off[MAX_N + 1];
__device__ __align__(16) int    g_pos[MAX_N];
__device__ __align__(16) int    g_part[MAX_N];
__device__ __align__(16) int    g_bsum[MAX_BLKS];
__device__ __align__(16) float  g_dinv[MAX_N];
__device__ __align__(16) int2   g_edge[MAX_E];       // (src, norm bits)
__device__ __align__(16) __half g_h1[MAX_N * H1D];   // fp16 storage for gather
__device__ __align__(16) float  g_a1[MAX_N * H1D];
__device__ __align__(16) __half g_h2[MAX_N * H2D];   // fp16 storage for gather

// ---------------- f32x2 helpers ----------------------------------------------
__device__ __forceinline__ uint64_t pk2(float lo, float hi) {
    uint64_t r; asm("mov.b64 %0, {%1,%2};" : "=l"(r) : "f"(lo), "f"(hi)); return r;
}
__device__ __forceinline__ void upk2(uint64_t v, float& lo, float& hi) {
    asm("mov.b64 {%0,%1}, %2;" : "=f"(lo), "=f"(hi) : "l"(v));
}
__device__ __forceinline__ void fma2(uint64_t& d, uint64_t a, uint64_t b) {
    asm("fma.rn.f32x2 %0, %1, %2, %0;" : "+l"(d) : "l"(a), "l"(b));
}

struct alignas(16) H8 { __half2 a, b, c, d; };  // 8 halves = 16B store

// ---------------- CSR build ---------------------------------------------------
__global__ void k_zero(int N) {
    int i = blockIdx.x * blockDim.x + threadIdx.x;
    if (i < N) g_indeg[i] = 0;
}

// vectorized count over [base, base+cnt): 2 edges/thread via int2
__global__ void k_count2(const int* __restrict__ ei, int E, int base, int cnt) {
    int e = base + (blockIdx.x * blockDim.x + threadIdx.x) * 2;
    int lim = base + cnt;
    if (e + 1 < lim) {
        int2 dd = *(const int2*)&ei[E + e];   // (E+e)*4 is 8B-aligned (E,e even)
        atomicAdd(&g_indeg[dd.x], 1);
        atomicAdd(&g_indeg[dd.y], 1);
    } else if (e < lim) {
        atomicAdd(&g_indeg[ei[E + e]], 1);
    }
}

__global__ void k_scan1(int N) {
    __shared__ int sm[SCAN_B];
    int gid = blockIdx.x * SCAN_B + threadIdx.x;
    int v = (gid < N) ? g_indeg[gid] : 0;
    sm[threadIdx.x] = v;
    __syncthreads();
#pragma unroll
    for (int s = 1; s < SCAN_B; s <<= 1) {
        int t = (threadIdx.x >= (unsigned)s) ? sm[threadIdx.x - s] : 0;
        __syncthreads();
        sm[threadIdx.x] += t;
        __syncthreads();
    }
    if (gid < N) g_part[gid] = sm[threadIdx.x] - v;
    if (threadIdx.x == SCAN_B - 1) g_bsum[blockIdx.x] = sm[threadIdx.x];
}

__global__ void k_scan2(int nb) {
    __shared__ int sm[256];
    int t = threadIdx.x;
    int v = (t < nb) ? g_bsum[t] : 0;
    sm[t] = v;
    __syncthreads();
#pragma unroll
    for (int s = 1; s < 256; s <<= 1) {
        int u = (t >= (unsigned)s) ? sm[t - s] : 0;
        __syncthreads();
        sm[t] += u;
        __syncthreads();
    }
    if (t < nb) g_bsum[t] = sm[t] - v;
}

// offsets + pos + dinv in one pass
__global__ void k_scan3(int N, int E) {
    int gid = blockIdx.x * blockDim.x + threadIdx.x;
    if (gid < N) {
        int o = g_part[gid] + g_bsum[gid / SCAN_B];
        g_off[gid] = o;
        g_pos[gid] = o;
        g_dinv[gid] = rsqrtf((float)g_indeg[gid] + 1.0f);
    }
    if (gid == 0) g_off[N] = E;
}

// vectorized fill: 2 edges/thread via int2
__global__ void k_fill2(const int* __restrict__ ei, int E) {
    int e = (blockIdx.x * blockDim.x + threadIdx.x) * 2;
    if (e + 1 < E) {
        int2 ss = *(const int2*)&ei[e];
        int2 dd = *(const int2*)&ei[E + e];
        int p0 = atomicAdd(&g_pos[dd.x], 1);
        int p1 = atomicAdd(&g_pos[dd.y], 1);
        g_edge[p0] = make_int2(ss.x, __float_as_int(g_dinv[ss.x] * g_dinv[dd.x]));
        g_edge[p1] = make_int2(ss.y, __float_as_int(g_dinv[ss.y] * g_dinv[dd.y]));
    } else if (e < E) {
        int s = ei[e], d = ei[E + e];
        int p = atomicAdd(&g_pos[d], 1);
        g_edge[p] = make_int2(s, __float_as_int(g_dinv[s] * g_dinv[d]));
    }
}

// ---------------- f32x2 GEMM: out(fp16) = (relu?)X @ W ------------------------
template <int KDIM, int ODIM, bool RELU_IN, int LAYER, int RT>
__global__ void __launch_bounds__(256, 2)
k_gemm2x(const float* __restrict__ Xparam, const float* __restrict__ Wg, int N) {
    constexpr int KC   = 32;
    constexpr int COLG = ODIM / 8;
    constexpr int ROWG = 256 / COLG;
    constexpr int TM   = ROWG * RT;
    constexpr int XP   = TM + 4;

    const float* X  = (LAYER == 1) ? Xparam : g_a1;
    __half*     out = (LAYER == 1) ? g_h1   : g_h2;

    __shared__ float Xs[KC][XP];
    __shared__ float Ws[KC][ODIM];

    int tid  = threadIdx.x;
    int row0 = blockIdx.x * TM;
    int tx = tid % COLG, ty = tid / COLG;
    int c0 = tx * 8, r0 = ty * RT;

    uint64_t acc[RT][4];
#pragma unroll
    for (int r = 0; r < RT; r++)
#pragma unroll
        for (int p = 0; p < 4; p++) acc[r][p] = 0ULL;

    for (int k0 = 0; k0 < KDIM; k0 += KC) {
        __syncthreads();
        {
            const float4* src = (const float4*)(Wg + (size_t)k0 * ODIM);
            float4* dst = (float4*)&Ws[0][0];
            for (int i = tid; i < KC * ODIM / 4; i += 256) dst[i] = src[i];
        }
        for (int i = tid; i < TM * (KC / 4); i += 256) {
            int r = i / (KC / 4);
            int q = i - r * (KC / 4);
            int gr = row0 + r;
            float4 v = make_float4(0.f, 0.f, 0.f, 0.f);
            if (gr < N) v = *(const float4*)(X + (size_t)gr * KDIM + k0 + q * 4);
            if (RELU_IN) {
                v.x = fmaxf(v.x, 0.f); v.y = fmaxf(v.y, 0.f);
                v.z = fmaxf(v.z, 0.f); v.w = fmaxf(v.w, 0.f);
            }
            Xs[q * 4 + 0][r] = v.x;
            Xs[q * 4 + 1][r] = v.y;
            Xs[q * 4 + 2][r] = v.z;
            Xs[q * 4 + 3][r] = v.w;
        }
        __syncthreads();

#pragma unroll 4
        for (int k = 0; k < KC; k++) {
            ulonglong2 wa = *(const ulonglong2*)&Ws[k][c0];
            ulonglong2 wb = *(const ulonglong2*)&Ws[k][c0 + 4];
            uint64_t wp[4] = {wa.x, wa.y, wb.x, wb.y};
#pragma unroll
            for (int rr = 0; rr < RT / 4; rr++) {
                float4 xv = *(const float4*)&Xs[k][r0 + rr * 4];
                uint64_t xb[4] = {pk2(xv.x, xv.x), pk2(xv.y, xv.y),
                                  pk2(xv.z, xv.z), pk2(xv.w, xv.w)};
#pragma unroll
                for (int r = 0; r < 4; r++)
#pragma unroll
                    for (int p = 0; p < 4; p++)
                        fma2(acc[rr * 4 + r][p], xb[r], wp[p]);
            }
        }
    }

#pragma unroll
    for (int r = 0; r < RT; r++) {
        int gr = row0 + r0 + r;
        if (gr >= N) continue;
        float4 o0, o1;
        upk2(acc[r][0], o0.x, o0.y); upk2(acc[r][1], o0.z, o0.w);
        upk2(acc[r][2], o1.x, o1.y); upk2(acc[r][3], o1.z, o1.w);
        H8 hpk;
        hpk.a = __floats2half2_rn(o0.x, o0.y);
        hpk.b = __floats2half2_rn(o0.z, o0.w);
        hpk.c = __floats2half2_rn(o1.x, o1.y);
        hpk.d = __floats2half2_rn(o1.z, o1.w);
        *(H8*)(out + (size_t)gr * ODIM + c0) = hpk;
    }
}

// -------- CSR gather layer 1 (F=64): warp-coop meta + half2 rows -------------
__global__ void k_gather64(const float* __restrict__ b, int N) {
    const __half2* h = (const __half2*)g_h1;
    float2*      out = (float2*)g_a1;
    constexpr int C2 = H1D / 2;

    int node = blockIdx.x * (blockDim.x >> 5) + (threadIdx.x >> 5);
    int lane = threadIdx.x & 31;
    if (node >= N) return;

    int beg = g_off[node];
    int end = g_off[node + 1];

    float ax = 0.0f, ay = 0.0f;
    int j = beg;
    for (; j + 32 <= end; j += 32) {
        int2 m = __ldg(&g_edge[j + lane]);
#pragma unroll 8
        for (int k = 0; k < 32; k++) {
            int   s  = __shfl_sync(0xffffffffu, m.x, k);
            float nm = __int_as_float(__shfl_sync(0xffffffffu, m.y, k));
            float2 v = __half22float2(__ldg(&h[(size_t)s * C2 + lane]));
            ax += v.x * nm;
            ay += v.y * nm;
        }
    }
    int rem = end - j;
    if (rem > 0) {
        int2 m = (lane < rem) ? __ldg(&g_edge[j + lane]) : make_int2(0, 0);
        for (int k = 0; k < rem; k++) {
            int   s  = __shfl_sync(0xffffffffu, m.x, k);
            float nm = __int_as_float(__shfl_sync(0xffffffffu, m.y, k));
            float2 v = __half22float2(__ldg(&h[(size_t)s * C2 + lane]));
            ax += v.x * nm;
            ay += v.y * nm;
        }
    }

    float di = g_dinv[node];
    float d2 = di * di;
    float2 hv = __half22float2(((const __half2*)g_h1)[(size_t)node * C2 + lane]);
    float2 bv = ((const float2*)b)[lane];
    float2 o;
    o.x = ax + hv.x * d2 + bv.x;
    o.y = ay + hv.y * d2 + bv.y;
    out[(size_t)node * C2 + lane] = o;
}

// -------- CSR gather layer 2 (F=32, fp16) + relu + classifier + log_softmax --
__global__ void k_gather32f(const float* __restrict__ b, const float* __restrict__ Wc,
                            const float* __restrict__ bc, float* __restrict__ outp,
                            int N) {
    constexpr int F = H2D;
    __shared__ float WcSm[H2D * NCLS];
    __shared__ float bcSm[NCLS];
    int tid = threadIdx.x;
    for (int i = tid; i < H2D * NCLS; i += blockDim.x) WcSm[i] = Wc[i];
    if (tid < NCLS) bcSm[tid] = bc[tid];
    __syncthreads();

    int node = blockIdx.x * (blockDim.x >> 5) + (tid >> 5);
    int lane = tid & 31;
    if (node >= N) return;

    const __half* h = g_h2;
    int beg = g_off[node];
    int end = g_off[node + 1];

    float acc = 0.0f;
    int j = beg;
    for (; j + 32 <= end; j += 32) {
        int2 m = __ldg(&g_edge[j + lane]);
#pragma unroll 8
        for (int k = 0; k < 32; k++) {
            int   s  = __shfl_sync(0xffffffffu, m.x, k);
            float nm = __int_as_float(__shfl_sync(0xffffffffu, m.y, k));
            acc += __half2float(__ldg(&h[(size_t)s * F + lane])) * nm;
        }
    }
    int rem = end - j;
    if (rem > 0) {
        int2 m = (lane < rem) ? __ldg(&g_edge[j + lane]) : make_int2(0, 0);
        for (int k = 0; k < rem; k++) {
            int   s  = __shfl_sync(0xffffffffu, m.x, k);
            float nm = __int_as_float(__shfl_sync(0xffffffffu, m.y, k));
            acc += __half2float(__ldg(&h[(size_t)s * F + lane])) * nm;
        }
    }

    float di = g_dinv[node];
    float x = acc + __half2float(h[(size_t)node * F + lane]) * di * di + b[lane];
    x = fmaxf(x, 0.0f);

    float p[NCLS];
#pragma unroll
    for (int c = 0; c < NCLS; c++) p[c] = x * WcSm[lane * NCLS + c];
#pragma unroll
    for (int s = 16; s > 0; s >>= 1)
#pragma unroll
        for (int c = 0; c < NCLS; c++)
            p[c] += __shfl_xor_sync(0xffffffffu, p[c], s);

    float lg[NCLS];
#pragma unroll
    for (int c = 0; c < NCLS; c++) lg[c] = p[c] + bcSm[c];
    float mx = lg[0];
#pragma unroll
    for (int c = 1; c < NCLS; c++) mx = fmaxf(mx, lg[c]);
    float sum = 0.0f;
#pragma unroll
    for (int c = 0; c < NCLS; c++) sum += __expf(lg[c] - mx);
    float lse = mx + logf(sum);

    if (lane < NCLS) outp[(size_t)node * NCLS + lane] = lg[lane] - lse;
}

// ---------------- launch (kernel launches ONLY; graph-capture clean) ---------
extern "C" void kernel_launch(void* const* d_in, const int* in_sizes, int n_in,
                              void* d_out, int out_size) {
    const float* feat = (const float*)d_in[0];
    const int*   ei   = (const int*)d_in[1];    // int32 (JAX x64 disabled)
    const float* W1   = (const float*)d_in[2];
    const float* b1   = (const float*)d_in[3];
    const float* W2   = (const float*)d_in[4];
    const float* b2   = (const float*)d_in[5];
    const float* Wc   = (const float*)d_in[6];
    const float* bc   = (const float*)d_in[7];

    int N = in_sizes[0] / FIN;
    int E = in_sizes[1] / 2;

    const int T = 256;
    int nb = (N + SCAN_B - 1) / SCAN_B;
    int half = (E / 2) & ~1;                 // even split for int2 alignment

    // gemm1 first (order-independent); count split so slot 4 profiles a half
    k_gemm2x<FIN, H1D, false, 1, 8><<<(N + 255) / 256, 256>>>(feat, W1, N);
    k_zero<<<(N + T - 1) / T, T>>>(N);
    k_count2<<<((half + 1) / 2 + T - 1) / T, T>>>(ei, E, 0, half);
    k_count2<<<((E - half + 1) / 2 + T - 1) / T, T>>>(ei, E, half, E - half);  // #4
    k_scan1<<<nb, SCAN_B>>>(N);
    k_scan2<<<1, 256>>>(nb);
    k_scan3<<<(N + T - 1) / T, T>>>(N, E);
    k_fill2<<<((E + 1) / 2 + T - 1) / T, T>>>(ei, E);

    // layer 1 aggregation
    k_gather64<<<(N + 7) / 8, 256>>>(b1, N);

    // layer 2 + fused classifier/log_softmax
    k_gemm2x<H1D, H2D, true, 2, 4><<<(N + 255) / 256, 256>>>(nullptr, W2, N);
    k_gather32f<<<(N + 7) / 8, 256>>>(b2, Wc, bc, (float*)d_out, N);
}

// round 17
// speedup vs baseline: 1.2754x; 1.0801x over previous
#include <cuda_runtime.h>
#include <cuda_fp16.h>
#include <math.h>
#include <stdint.h>

#define MAX_E 3200000
#define MAX_N 100000
#define FIN 128
#define H1D 64
#define H2D 32
#define NCLS 10
#define SCAN_B 512
#define MAX_BLKS ((MAX_N + SCAN_B) / SCAN_B + 2)

// ---------------- scratch (device globals; referenced directly, no host APIs)
__device__ __align__(16) int    g_indeg[MAX_N];
__device__ __align__(16) int    g_off[MAX_N + 1];
__device__ __align__(16) int    g_pos[MAX_N];
__device__ __align__(16) int    g_part[MAX_N];
__device__ __align__(16) int    g_bsum[MAX_BLKS];
__device__ __align__(16) float  g_dinv[MAX_N];
__device__ __align__(16) int    g_esrc[MAX_E];       // src only (4B/edge)
__device__ __align__(16) __half g_h1[MAX_N * H1D];   // h1 * dinv[row], fp16
__device__ __align__(16) float  g_a1[MAX_N * H1D];
__device__ __align__(16) __half g_h2[MAX_N * H2D];   // h2 * dinv[row], fp16

// ---------------- f32x2 helpers ----------------------------------------------
__device__ __forceinline__ uint64_t pk2(float lo, float hi) {
    uint64_t r; asm("mov.b64 %0, {%1,%2};" : "=l"(r) : "f"(lo), "f"(hi)); return r;
}
__device__ __forceinline__ void upk2(uint64_t v, float& lo, float& hi) {
    asm("mov.b64 {%0,%1}, %2;" : "=f"(lo), "=f"(hi) : "l"(v));
}
__device__ __forceinline__ void fma2(uint64_t& d, uint64_t a, uint64_t b) {
    asm("fma.rn.f32x2 %0, %1, %2, %0;" : "+l"(d) : "l"(a), "l"(b));
}

struct alignas(16) H8 { __half2 a, b, c, d; };  // 8 halves = 16B store

// ---------------- CSR build ---------------------------------------------------
__global__ void k_zero(int N) {
    int i = blockIdx.x * blockDim.x + threadIdx.x;
    if (i < N) g_indeg[i] = 0;
}

// vectorized count: 2 edges/thread via int2
__global__ void k_count2(const int* __restrict__ ei, int E) {
    int e = (blockIdx.x * blockDim.x + threadIdx.x) * 2;
    if (e + 1 < E) {
        int2 dd = *(const int2*)&ei[E + e];
        atomicAdd(&g_indeg[dd.x], 1);
        atomicAdd(&g_indeg[dd.y], 1);
    } else if (e < E) {
        atomicAdd(&g_indeg[ei[E + e]], 1);
    }
}

__global__ void k_scan1(int N) {
    __shared__ int sm[SCAN_B];
    int gid = blockIdx.x * SCAN_B + threadIdx.x;
    int v = (gid < N) ? g_indeg[gid] : 0;
    sm[threadIdx.x] = v;
    __syncthreads();
#pragma unroll
    for (int s = 1; s < SCAN_B; s <<= 1) {
        int t = (threadIdx.x >= (unsigned)s) ? sm[threadIdx.x - s] : 0;
        __syncthreads();
        sm[threadIdx.x] += t;
        __syncthreads();
    }
    if (gid < N) g_part[gid] = sm[threadIdx.x] - v;
    if (threadIdx.x == SCAN_B - 1) g_bsum[blockIdx.x] = sm[threadIdx.x];
}

__global__ void k_scan2(int nb) {
    __shared__ int sm[256];
    int t = threadIdx.x;
    int v = (t < nb) ? g_bsum[t] : 0;
    sm[t] = v;
    __syncthreads();
#pragma unroll
    for (int s = 1; s < 256; s <<= 1) {
        int u = (t >= (unsigned)s) ? sm[t - s] : 0;
        __syncthreads();
        sm[t] += u;
        __syncthreads();
    }
    if (t < nb) g_bsum[t] = sm[t] - v;
}

// offsets + pos + dinv in one pass
__global__ void k_scan3(int N, int E) {
    int gid = blockIdx.x * blockDim.x + threadIdx.x;
    if (gid < N) {
        int o = g_part[gid] + g_bsum[gid / SCAN_B];
        g_off[gid] = o;
        g_pos[gid] = o;
        g_dinv[gid] = rsqrtf((float)g_indeg[gid] + 1.0f);
    }
    if (gid == 0) g_off[N] = E;
}

// fill: src-only records, no dinv loads; 2 edges/thread
__global__ void k_fill2(const int* __restrict__ ei, int E) {
    int e = (blockIdx.x * blockDim.x + threadIdx.x) * 2;
    if (e + 1 < E) {
        int2 ss = *(const int2*)&ei[e];
        int2 dd = *(const int2*)&ei[E + e];
        int p0 = atomicAdd(&g_pos[dd.x], 1);
        int p1 = atomicAdd(&g_pos[dd.y], 1);
        g_esrc[p0] = ss.x;
        g_esrc[p1] = ss.y;
    } else if (e < E) {
        int p = atomicAdd(&g_pos[ei[E + e]], 1);
        g_esrc[p] = ei[e];
    }
}

// ------- f32x2 GEMM: out(fp16) = dinv[row] * ((relu?)X @ W) -------------------
template <int KDIM, int ODIM, bool RELU_IN, int LAYER, int RT>
__global__ void __launch_bounds__(256, 2)
k_gemm2x(const float* __restrict__ Xparam, const float* __restrict__ Wg, int N) {
    constexpr int KC   = 32;
    constexpr int COLG = ODIM / 8;
    constexpr int ROWG = 256 / COLG;
    constexpr int TM   = ROWG * RT;
    constexpr int XP   = TM + 4;

    const float* X  = (LAYER == 1) ? Xparam : g_a1;
    __half*     out = (LAYER == 1) ? g_h1   : g_h2;

    __shared__ float Xs[KC][XP];
    __shared__ float Ws[KC][ODIM];

    int tid  = threadIdx.x;
    int row0 = blockIdx.x * TM;
    int tx = tid % COLG, ty = tid / COLG;
    int c0 = tx * 8, r0 = ty * RT;

    uint64_t acc[RT][4];
#pragma unroll
    for (int r = 0; r < RT; r++)
#pragma unroll
        for (int p = 0; p < 4; p++) acc[r][p] = 0ULL;

    for (int k0 = 0; k0 < KDIM; k0 += KC) {
        __syncthreads();
        {
            const float4* src = (const float4*)(Wg + (size_t)k0 * ODIM);
            float4* dst = (float4*)&Ws[0][0];
            for (int i = tid; i < KC * ODIM / 4; i += 256) dst[i] = src[i];
        }
        for (int i = tid; i < TM * (KC / 4); i += 256) {
            int r = i / (KC / 4);
            int q = i - r * (KC / 4);
            int gr = row0 + r;
            float4 v = make_float4(0.f, 0.f, 0.f, 0.f);
            if (gr < N) v = *(const float4*)(X + (size_t)gr * KDIM + k0 + q * 4);
            if (RELU_IN) {
                v.x = fmaxf(v.x, 0.f); v.y = fmaxf(v.y, 0.f);
                v.z = fmaxf(v.z, 0.f); v.w = fmaxf(v.w, 0.f);
            }
            Xs[q * 4 + 0][r] = v.x;
            Xs[q * 4 + 1][r] = v.y;
            Xs[q * 4 + 2][r] = v.z;
            Xs[q * 4 + 3][r] = v.w;
        }
        __syncthreads();

#pragma unroll 4
        for (int k = 0; k < KC; k++) {
            ulonglong2 wa = *(const ulonglong2*)&Ws[k][c0];
            ulonglong2 wb = *(const ulonglong2*)&Ws[k][c0 + 4];
            uint64_t wp[4] = {wa.x, wa.y, wb.x, wb.y};
#pragma unroll
            for (int rr = 0; rr < RT / 4; rr++) {
                float4 xv = *(const float4*)&Xs[k][r0 + rr * 4];
                uint64_t xb[4] = {pk2(xv.x, xv.x), pk2(xv.y, xv.y),
                                  pk2(xv.z, xv.z), pk2(xv.w, xv.w)};
#pragma unroll
                for (int r = 0; r < 4; r++)
#pragma unroll
                    for (int p = 0; p < 4; p++)
                        fma2(acc[rr * 4 + r][p], xb[r], wp[p]);
            }
        }
    }

#pragma unroll
    for (int r = 0; r < RT; r++) {
        int gr = row0 + r0 + r;
        if (gr >= N) continue;
        float di = g_dinv[gr];                  // fold dinv[row] into h storage
        float4 o0, o1;
        upk2(acc[r][0], o0.x, o0.y); upk2(acc[r][1], o0.z, o0.w);
        upk2(acc[r][2], o1.x, o1.y); upk2(acc[r][3], o1.z, o1.w);
        H8 hpk;
        hpk.a = __floats2half2_rn(o0.x * di, o0.y * di);
        hpk.b = __floats2half2_rn(o0.z * di, o0.w * di);
        hpk.c = __floats2half2_rn(o1.x * di, o1.y * di);
        hpk.d = __floats2half2_rn(o1.z * di, o1.w * di);
        *(H8*)(out + (size_t)gr * ODIM + c0) = hpk;
    }
}

// -------- CSR gather layer 1 (F=64): a1 = dinv*(sum hs[src] + hs[node]) + b --
__global__ void k_gather64(const float* __restrict__ b, int N) {
    const __half2* h = (const __half2*)g_h1;
    float2*      out = (float2*)g_a1;
    constexpr int C2 = H1D / 2;

    int node = blockIdx.x * (blockDim.x >> 5) + (threadIdx.x >> 5);
    int lane = threadIdx.x & 31;
    if (node >= N) return;

    int beg = g_off[node];
    int end = g_off[node + 1];

    float ax = 0.0f, ay = 0.0f;
    int j = beg;
    for (; j + 32 <= end; j += 32) {
        int m = __ldg(&g_esrc[j + lane]);
#pragma unroll 8
        for (int k = 0; k < 32; k++) {
            int s = __shfl_sync(0xffffffffu, m, k);
            float2 v = __half22float2(__ldg(&h[(size_t)s * C2 + lane]));
            ax += v.x;
            ay += v.y;
        }
    }
    int rem = end - j;
    if (rem > 0) {
        int m = (lane < rem) ? __ldg(&g_esrc[j + lane]) : 0;
        for (int k = 0; k < rem; k++) {
            int s = __shfl_sync(0xffffffffu, m, k);
            float2 v = __half22float2(__ldg(&h[(size_t)s * C2 + lane]));
            ax += v.x;
            ay += v.y;
        }
    }

    float di = g_dinv[node];
    float2 hv = __half22float2(h[(size_t)node * C2 + lane]);
    float2 bv = ((const float2*)b)[lane];
    float2 o;
    o.x = di * (ax + hv.x) + bv.x;
    o.y = di * (ay + hv.y) + bv.y;
    out[(size_t)node * C2 + lane] = o;
}

// -------- CSR gather layer 2 (F=32) + relu + classifier + log_softmax --------
__global__ void k_gather32f(const float* __restrict__ b, const float* __restrict__ Wc,
                            const float* __restrict__ bc, float* __restrict__ outp,
                            int N) {
    constexpr int F = H2D;
    __shared__ float WcSm[H2D * NCLS];
    __shared__ float bcSm[NCLS];
    int tid = threadIdx.x;
    for (int i = tid; i < H2D * NCLS; i += blockDim.x) WcSm[i] = Wc[i];
    if (tid < NCLS) bcSm[tid] = bc[tid];
    __syncthreads();

    int node = blockIdx.x * (blockDim.x >> 5) + (tid >> 5);
    int lane = tid & 31;
    if (node >= N) return;

    const __half* h = g_h2;
    int beg = g_off[node];
    int end = g_off[node + 1];

    float acc = 0.0f;
    int j = beg;
    for (; j + 32 <= end; j += 32) {
        int m = __ldg(&g_esrc[j + lane]);
#pragma unroll 8
        for (int k = 0; k < 32; k++) {
            int s = __shfl_sync(0xffffffffu, m, k);
            acc += __half2float(__ldg(&h[(size_t)s * F + lane]));
        }
    }
    int rem = end - j;
    if (rem > 0) {
        int m = (lane < rem) ? __ldg(&g_esrc[j + lane]) : 0;
        for (int k = 0; k < rem; k++) {
            int s = __shfl_sync(0xffffffffu, m, k);
            acc += __half2float(__ldg(&h[(size_t)s * F + lane]));
        }
    }

    float di = g_dinv[node];
    float x = di * (acc + __half2float(h[(size_t)node * F + lane])) + b[lane];
    x = fmaxf(x, 0.0f);

    float p[NCLS];
#pragma unroll
    for (int c = 0; c < NCLS; c++) p[c] = x * WcSm[lane * NCLS + c];
#pragma unroll
    for (int s = 16; s > 0; s >>= 1)
#pragma unroll
        for (int c = 0; c < NCLS; c++)
            p[c] += __shfl_xor_sync(0xffffffffu, p[c], s);

    float lg[NCLS];
#pragma unroll
    for (int c = 0; c < NCLS; c++) lg[c] = p[c] + bcSm[c];
    float mx = lg[0];
#pragma unroll
    for (int c = 1; c < NCLS; c++) mx = fmaxf(mx, lg[c]);
    float sum = 0.0f;
#pragma unroll
    for (int c = 0; c < NCLS; c++) sum += __expf(lg[c] - mx);
    float lse = mx + logf(sum);

    if (lane < NCLS) outp[(size_t)node * NCLS + lane] = lg[lane] - lse;
}

// ---------------- launch (kernel launches ONLY; graph-capture clean) ---------
extern "C" void kernel_launch(void* const* d_in, const int* in_sizes, int n_in,
                              void* d_out, int out_size) {
    const float* feat = (const float*)d_in[0];
    const int*   ei   = (const int*)d_in[1];    // int32 (JAX x64 disabled)
    const float* W1   = (const float*)d_in[2];
    const float* b1   = (const float*)d_in[3];
    const float* W2   = (const float*)d_in[4];
    const float* b2   = (const float*)d_in[5];
    const float* Wc   = (const float*)d_in[6];
    const float* bc   = (const float*)d_in[7];

    int N = in_sizes[0] / FIN;
    int E = in_sizes[1] / 2;

    const int T = 256;
    int nb = (N + SCAN_B - 1) / SCAN_B;

    // CSR build (dinv must exist before gemm1's scaled epilogue)
    k_zero<<<(N + T - 1) / T, T>>>(N);
    k_count2<<<((E + 1) / 2 + T - 1) / T, T>>>(ei, E);
    k_scan1<<<nb, SCAN_B>>>(N);
    k_scan2<<<1, 256>>>(nb);
    k_scan3<<<(N + T - 1) / T, T>>>(N, E);
    k_fill2<<<((E + 1) / 2 + T - 1) / T, T>>>(ei, E);

    // layer 1
    k_gemm2x<FIN, H1D, false, 1, 8><<<(N + 255) / 256, 256>>>(feat, W1, N);
    k_gather64<<<(N + 7) / 8, 256>>>(b1, N);

    // layer 2 + fused classifier/log_softmax
    k_gemm2x<H1D, H2D, true, 2, 4><<<(N + 255) / 256, 256>>>(nullptr, W2, N);
    k_gather32f<<<(N + 7) / 8, 256>>>(b2, Wc, bc, (float*)d_out, N);
}